// round 9
// baseline (speedup 1.0000x reference)
#include <cuda_runtime.h>
#include <math.h>

#define T_STEPS 512
#define B_SZ    128
#define NI_SZ   512
#define D_SZ    512
#define G4_SZ   2048   // 4*D

typedef unsigned long long u64;

// Scratch (device globals: allocation-free rule workaround)
__device__ float g_intern[(size_t)T_STEPS * B_SZ * G4_SZ];
__device__ float g_hT[2][(size_t)D_SZ * B_SZ];   // transposed h mirror [k][b], ping-pong
__device__ unsigned g_flag[128 * 32];            // per-CTA produce flag (128B padded)

__device__ __forceinline__ void ffma2(u64 &d, u64 a, u64 b) {
    asm("fma.rn.f32x2 %0, %1, %2, %0;" : "+l"(d) : "l"(a), "l"(b));
}
__device__ __forceinline__ u64 dup2(float f) {
    u64 d; asm("mov.b64 %0, {%1, %1};" : "=l"(d) : "f"(f)); return d;
}
__device__ __forceinline__ u64 add2(u64 a, u64 b) {
    u64 d; asm("add.rn.f32x2 %0, %1, %2;" : "=l"(d) : "l"(a), "l"(b)); return d;
}
__device__ __forceinline__ float2 unpack2(u64 a) {
    float2 f; asm("mov.b64 {%0, %1}, %2;" : "=f"(f.x), "=f"(f.y) : "l"(a)); return f;
}
__device__ __forceinline__ unsigned ld_acq(const unsigned* p) {
    unsigned v;
    asm volatile("ld.acquire.gpu.global.u32 %0, [%1];" : "=r"(v) : "l"(p) : "memory");
    return v;
}
__device__ __forceinline__ void st_release_exch(unsigned* p, unsigned v) {
    unsigned tmp;
    asm volatile("atom.release.gpu.global.exch.b32 %0, [%1], %2;"
                 : "=r"(tmp) : "l"(p), "r"(v) : "memory");
}
__device__ __forceinline__ void bar_pair(int id) {
    asm volatile("bar.sync %0, 64;" :: "r"(id) : "memory");
}

// ---------------------------------------------------------------------------
// h0 transpose: g_hT[0][k*128+b] = h0[b*512+k]
// ---------------------------------------------------------------------------
__global__ __launch_bounds__(256)
void h0_transpose_kernel(const float* __restrict__ h0)
{
    int idx = blockIdx.x * 256 + threadIdx.x;   // 65536 total
    int k = idx >> 7, b = idx & 127;
    g_hT[0][idx] = h0[b * D_SZ + k];
}

// ---------------------------------------------------------------------------
// Phase 1: intern = X@Wf + bf, 128x128x8 tile, FFMA2 (at FFMA2 roofline)
// ---------------------------------------------------------------------------
__global__ __launch_bounds__(256)
void gemm_intern_kernel(const float* __restrict__ X,
                        const float* __restrict__ Wf,
                        const float* __restrict__ bf)
{
    __shared__ __align__(16) float As[8][128];
    __shared__ __align__(16) float Bs[8][128];

    const int t  = threadIdx.x;
    const int tx = t & 15;
    const int ty = t >> 4;
    const int m0 = blockIdx.y * 128;
    const int n0 = blockIdx.x * 128;

    const int arow = t >> 1, acol = (t & 1) * 4;
    const int brow = t >> 5, bcol = (t & 31) * 4;

    const float* Aptr = X  + (size_t)(m0 + arow) * NI_SZ + acol;
    const float* Bptr = Wf + (size_t)brow * G4_SZ + n0 + bcol;

    u64 acc[8][4];
    #pragma unroll
    for (int i = 0; i < 8; i++)
        #pragma unroll
        for (int j = 0; j < 4; j++) acc[i][j] = 0ull;

    for (int k0 = 0; k0 < NI_SZ; k0 += 8) {
        float4 av = *(const float4*)(Aptr + k0);
        float4 bv = *(const float4*)(Bptr + (size_t)k0 * G4_SZ);
        __syncthreads();
        As[acol + 0][arow] = av.x;
        As[acol + 1][arow] = av.y;
        As[acol + 2][arow] = av.z;
        As[acol + 3][arow] = av.w;
        *(float4*)&Bs[brow][bcol] = bv;
        __syncthreads();
        #pragma unroll
        for (int k = 0; k < 8; k++) {
            float4 a0 = *(const float4*)&As[k][ty * 4];
            float4 a1 = *(const float4*)&As[k][64 + ty * 4];
            ulonglong2 bA = *(const ulonglong2*)&Bs[k][tx * 4];
            ulonglong2 bB = *(const ulonglong2*)&Bs[k][64 + tx * 4];
            u64 ad[8] = {dup2(a0.x), dup2(a0.y), dup2(a0.z), dup2(a0.w),
                         dup2(a1.x), dup2(a1.y), dup2(a1.z), dup2(a1.w)};
            #pragma unroll
            for (int i = 0; i < 8; i++) {
                ffma2(acc[i][0], ad[i], bA.x);
                ffma2(acc[i][1], ad[i], bA.y);
                ffma2(acc[i][2], ad[i], bB.x);
                ffma2(acc[i][3], ad[i], bB.y);
            }
        }
    }

    float4 bias0 = *(const float4*)&bf[n0 + tx * 4];
    float4 bias1 = *(const float4*)&bf[n0 + 64 + tx * 4];
    #pragma unroll
    for (int i = 0; i < 8; i++) {
        int m = m0 + (i < 4 ? ty * 4 + i : 64 + ty * 4 + (i - 4));
        float* out = g_intern + (size_t)m * G4_SZ + n0;
        float2 p0 = unpack2(acc[i][0]), p1 = unpack2(acc[i][1]);
        float2 p2 = unpack2(acc[i][2]), p3 = unpack2(acc[i][3]);
        float4 v0 = make_float4(p0.x + bias0.x, p0.y + bias0.y,
                                p1.x + bias0.z, p1.y + bias0.w);
        float4 v1 = make_float4(p2.x + bias1.x, p2.y + bias1.y,
                                p3.x + bias1.z, p3.y + bias1.w);
        *(float4*)(out + tx * 4)      = v0;
        *(float4*)(out + 64 + tx * 4) = v1;
    }
}

// ---------------------------------------------------------------------------
// Phase 2: persistent LSTM. 128 CTAs (1/SM), 512 threads = 16 warps.
// NEW fold structure: warp w -> (ks = w>>1) k-split of 64 rows x (hf = w&1)
// gate-half. 16 u64 accs/thread. Single store phase into 8 partial arrays
// (region R(ks) aliases exactly the h rows the pair consumed -> pair-scoped
// named barriers instead of 2 full syncthreads). Epilogue sums 8 arrays.
// ---------------------------------------------------------------------------
#define THREADS 512
#define WROW 68                    // [k][8 jp x 4 g u64, skewed]
#define HROW 36                    // [k][32 b + pad]
#define WR_F (512 * WROW)          // 34816 floats
#define H_F  (512 * HROW)          // 18432 floats (= 8 regions * 2304)
#define SMEM_F (WR_F + H_F)        // 53248 floats = 212992 bytes

__global__ __launch_bounds__(THREADS, 1)
void lstm_persistent_kernel(const float* __restrict__ hT0,
                            const float* __restrict__ c0,
                            const float* __restrict__ iv,
                            const float* __restrict__ Wr,
                            float* __restrict__ Y,
                            float* __restrict__ C,
                            float* __restrict__ d_fin)
{
    extern __shared__ __align__(16) float smem[];
    float* Ws = smem;                 // Wr slice, persistent
    float* Hs = smem + WR_F;          // h buffer; R(ks) = Hs + ks*2304 aliases rows [64ks,64ks+64)

    const int t    = threadIdx.x;
    const int bid  = blockIdx.x;        // 0..127
    const int j0   = (bid & 31) * 16;
    const int bm0  = (bid >> 5) * 32;
    const int grp  = bid >> 5;

    const int w    = t >> 5;            // warp 0..15
    const int lane = t & 31;
    const int ks   = w >> 1;            // k-split (64 k each)
    const int hf   = w & 1;             // gate-half: gates {2hf, 2hf+1}
    const int jp   = lane >> 2;         // j-pair (0..7)
    const int bg   = lane & 3;          // b octet (8 b's)
    const int wboff = jp * 8 + (jp >> 2) * 4 + hf * 4;
    const int hboff = bg * 8;

    // epilogue cell (one per thread; c lives in a register)
    const int b_l = t >> 4, jl = t & 15;
    const int b_g = bm0 + b_l, j_g = j0 + jl;
    const int lane_src = (jl >> 1) * 4 + (b_l >> 3);
    const int eoff = lane_src * 68 + (b_l & 7) * 4;   // within region; +32 for gates 2,3
    const int p_odd = jl & 1;
    float c_reg = __ldcg(c0 + (size_t)b_g * D_SZ + j_g);

    // ---- flags: own base + the 2 producers whose y-tiles this warp stages
    const unsigned fbase = g_flag[bid * 32];
    const unsigned* fp0 = &g_flag[(grp * 32 + 2 * w) * 32];
    const unsigned* fp1 = &g_flag[(grp * 32 + 2 * w + 1) * 32];

    // ---- one-time: load Wr slice into smem (16 float4 per thread)
    #pragma unroll
    for (int u = 0; u < 16; u++) {
        int idx = u * THREADS + t;
        int kk2 = idx >> 4;
        int rem = idx & 15;
        int g = rem >> 2, jqs = rem & 3;
        float4 v = __ldcg((const float4*)(Wr + (size_t)kk2 * G4_SZ + g * D_SZ + j0 + jqs * 4));
        int jpA = jqs * 2, jpB = jqs * 2 + 1;
        float* dA = Ws + kk2 * WROW + jpA * 8 + (jpA >> 2) * 4 + g * 2;
        float* dB = Ws + kk2 * WROW + jpB * 8 + (jpB >> 2) * 4 + g * 2;
        dA[0] = v.x; dA[1] = v.y;
        dB[0] = v.z; dB[1] = v.w;
    }
    __syncthreads();

    // warp-local h staging map: warp w stages rows [32w, 32w+32)
    const int s_r0 = w * 32 + (lane >> 3);   // + 4 per u
    const int s_bq = (lane & 7) * 4;

    // prefetch step 0 epilogue operands
    const float* itp = g_intern + (size_t)b_g * G4_SZ + j_g;
    float in0 = __ldcg(itp), in1 = __ldcg(itp + 512);
    float in2 = __ldcg(itp + 1024), in3 = __ldcg(itp + 1536);
    float mval = __ldcg(iv + b_g);

    for (int step = 0; step < T_STEPS; step++) {
        const float* hT_in  = g_hT[step & 1];
        float*       hT_out = g_hT[(step + 1) & 1];

        // ---- per-warp wait: my 2 producers must have published h(step)
        if (step > 0) {
            unsigned need = fbase + (unsigned)step;
            unsigned v0 = ld_acq(fp0), v1 = ld_acq(fp1);
            while (((int)(v0 - need) < 0) | ((int)(v1 - need) < 0)) {
                __nanosleep(20);
                v0 = ld_acq(fp0); v1 = ld_acq(fp1);
            }
        }

        // ---- stage own 32 rows (ldcg dodges stale L1 on ping-pong buffer)
        {
            float4 hv[8];
            #pragma unroll
            for (int u = 0; u < 8; u++)
                hv[u] = __ldcg((const float4*)(hT_in +
                          (size_t)(s_r0 + u * 4) * B_SZ + bm0 + s_bq));
            #pragma unroll
            for (int u = 0; u < 8; u++)
                *(float4*)(Hs + (s_r0 + u * 4) * HROW + s_bq) = hv[u];
        }
        bar_pair(1 + ks);   // pair (ks,0),(ks,1): both halves of rows [64ks,+64) staged

        // ---- mainloop: 64 k, gates {2hf, 2hf+1}; 3 LDS.128 + 16 FFMA2 per k
        u64 acc[8][2];
        #pragma unroll
        for (int i = 0; i < 8; i++) { acc[i][0] = 0ull; acc[i][1] = 0ull; }

        const float* hrow = Hs + (ks * 64) * HROW + hboff;
        const float* wrow = Ws + (ks * 64) * WROW + wboff;
        #pragma unroll 8
        for (int m = 0; m < 64; m++) {
            float4 hA = *(const float4*)(hrow);
            float4 hB = *(const float4*)(hrow + 4);
            ulonglong2 wv = *(const ulonglong2*)(wrow);   // (g_lo pair, g_hi pair)
            hrow += HROW; wrow += WROW;
            u64 hd[8] = {dup2(hA.x), dup2(hA.y), dup2(hA.z), dup2(hA.w),
                         dup2(hB.x), dup2(hB.y), dup2(hB.z), dup2(hB.w)};
            #pragma unroll
            for (int i = 0; i < 8; i++) {
                ffma2(acc[i][0], hd[i], wv.x);
                ffma2(acc[i][1], hd[i], wv.y);
            }
        }

        // ---- single store phase into R(ks) (aliases rows the pair just read)
        bar_pair(1 + ks);
        {
            float* p = Hs + ks * 2304 + lane * 68 + hf * 32;
            #pragma unroll
            for (int i = 0; i < 8; i++)
                *(ulonglong2*)(p + i * 4) = make_ulonglong2(acc[i][0], acc[i][1]);
        }
        __syncthreads();

        // ---- fused epilogue: sum 8 partial arrays (16 LDS.128 + add2 trees)
        float y_out;
        {
            u64 sA0 = 0ull, sA1 = 0ull, sB0 = 0ull, sB1 = 0ull;
            #pragma unroll
            for (int r = 0; r < 8; r++) {
                const float* p = Hs + r * 2304 + eoff;
                ulonglong2 vA = *(const ulonglong2*)(p);        // gates 0,1
                ulonglong2 vB = *(const ulonglong2*)(p + 32);   // gates 2,3
                sA0 = add2(sA0, vA.x);
                sA1 = add2(sA1, vA.y);
                sB0 = add2(sB0, vB.x);
                sB1 = add2(sB1, vB.y);
            }
            float2 a0 = unpack2(sA0), a1 = unpack2(sA1);
            float2 b0 = unpack2(sB0), b1 = unpack2(sB1);
            float z0 = p_odd ? a0.y : a0.x;
            float z1 = p_odd ? a1.y : a1.x;
            float z2 = p_odd ? b0.y : b0.x;
            float z3 = p_odd ? b1.y : b1.x;

            float zc = z0 + in0;
            float zi = z1 + in1;
            float zf = z2 + in2;
            float zo = z3 + in3;

            zc = fminf(fmaxf(zc, -30.f), 30.f);
            float ec  = __expf(-2.f * zc);
            float cin = (1.f - ec) / (1.f + ec);
            float ig  = 1.f / (1.f + __expf(-zi));
            float fg  = 1.f / (1.f + __expf(-zf));
            float og  = 1.f / (1.f + __expf(-zo));

            float m    = mval;
            float cnew = m * (c_reg * fg + cin * ig) + (1.f - m) * c_reg;
            c_reg = cnew;
            float ct = fminf(fmaxf(cnew, -30.f), 30.f);
            float e2 = __expf(-2.f * ct);
            y_out = m * (og * (1.f - e2) / (1.f + e2));
        }

        // ---- publish h(step+1): direct scattered STG (own cell), then flag
        if (step + 1 < T_STEPS)
            hT_out[(size_t)j_g * B_SZ + b_g] = y_out;
        __syncthreads();   // all hT STGs issued + all region reads complete
        if (step + 1 < T_STEPS && t == 0)
            st_release_exch(&g_flag[bid * 32], fbase + (unsigned)step + 1);

        // ---- deferred gmem writes (off the publish critical path)
        {
            size_t o = (size_t)step * (B_SZ * D_SZ) + (size_t)b_g * D_SZ + j_g;
            Y[o] = y_out;
            C[o] = c_reg;
            if (step == T_STEPS - 1) d_fin[(size_t)b_g * D_SZ + j_g] = c_reg;
        }

        // ---- prefetch next step's epilogue operands
        if (step + 1 < T_STEPS) {
            const float* itn = g_intern + (size_t)(step + 1) * (B_SZ * G4_SZ)
                             + (size_t)b_g * G4_SZ + j_g;
            in0 = __ldcg(itn);
            in1 = __ldcg(itn + 512);
            in2 = __ldcg(itn + 1024);
            in3 = __ldcg(itn + 1536);
            mval = __ldcg(iv + (size_t)(step + 1) * B_SZ + b_g);
        }
    }
}

// ---------------------------------------------------------------------------
// Launch. Inputs: X, Wf, Wr, bf, i, h0, c0. Output: Y[T,B,D]|C[T,B,D]|d[B,D]
// ---------------------------------------------------------------------------
extern "C" void kernel_launch(void* const* d_in, const int* in_sizes, int n_in,
                              void* d_out, int out_size)
{
    (void)in_sizes; (void)n_in; (void)out_size;
    const float* X  = (const float*)d_in[0];
    const float* Wf = (const float*)d_in[1];
    const float* Wr = (const float*)d_in[2];
    const float* bf = (const float*)d_in[3];
    const float* iv = (const float*)d_in[4];
    const float* h0 = (const float*)d_in[5];
    const float* c0 = (const float*)d_in[6];

    float* out  = (float*)d_out;
    float* Y    = out;
    float* C    = out + (size_t)T_STEPS * B_SZ * D_SZ;
    float* dfin = C   + (size_t)T_STEPS * B_SZ * D_SZ;

    float* hT0; cudaGetSymbolAddress((void**)&hT0, g_hT);

    h0_transpose_kernel<<<256, 256>>>(h0);

    dim3 g1(G4_SZ / 128, (T_STEPS * B_SZ) / 128);  // (16, 512)
    gemm_intern_kernel<<<g1, 256>>>(X, Wf, bf);

    cudaFuncSetAttribute(lstm_persistent_kernel,
                         cudaFuncAttributeMaxDynamicSharedMemorySize,
                         SMEM_F * (int)sizeof(float));
    lstm_persistent_kernel<<<128, THREADS, SMEM_F * sizeof(float)>>>(
        hT0, c0, iv, Wr, Y, C, dfin);
}

// round 12
// speedup vs baseline: 1.1824x; 1.1824x over previous
#include <cuda_runtime.h>
#include <cuda_bf16.h>
#include <cstdint>
#include <math.h>

#define T_STEPS 512
#define B_SZ    128
#define NI_SZ   512
#define D_SZ    512
#define G4_SZ   2048   // 4*D

typedef unsigned long long u64;

// Scratch (device globals: allocation-free rule workaround)
__device__ float g_intern[(size_t)T_STEPS * B_SZ * G4_SZ];
__device__ float g_hT[2][(size_t)D_SZ * B_SZ];   // transposed h mirror [k][b], ping-pong
__device__ unsigned g_flag[128 * 32];            // per-CTA produce flag (128B padded)
// bf16 split planes for the tensor-core GEMM
__device__ __nv_bfloat16 g_Xh[(size_t)T_STEPS * B_SZ * NI_SZ];
__device__ __nv_bfloat16 g_Xl[(size_t)T_STEPS * B_SZ * NI_SZ];
__device__ __nv_bfloat16 g_Bh[(size_t)G4_SZ * NI_SZ];   // Wf^T hi  [n][k]
__device__ __nv_bfloat16 g_Bl[(size_t)G4_SZ * NI_SZ];   // Wf^T lo

// ---------------- scalar packed-f32 helpers (recurrence) ----------------
__device__ __forceinline__ void ffma2(u64 &d, u64 a, u64 b) {
    asm("fma.rn.f32x2 %0, %1, %2, %0;" : "+l"(d) : "l"(a), "l"(b));
}
__device__ __forceinline__ u64 dup2(float f) {
    u64 d; asm("mov.b64 %0, {%1, %1};" : "=l"(d) : "f"(f)); return d;
}
__device__ __forceinline__ u64 add2(u64 a, u64 b) {
    u64 d; asm("add.rn.f32x2 %0, %1, %2;" : "=l"(d) : "l"(a), "l"(b)); return d;
}
__device__ __forceinline__ float2 unpack2(u64 a) {
    float2 f; asm("mov.b64 {%0, %1}, %2;" : "=f"(f.x), "=f"(f.y) : "l"(a)); return f;
}
__device__ __forceinline__ unsigned ld_acq(const unsigned* p) {
    unsigned v;
    asm volatile("ld.acquire.gpu.global.u32 %0, [%1];" : "=r"(v) : "l"(p) : "memory");
    return v;
}
__device__ __forceinline__ void st_release_exch(unsigned* p, unsigned v) {
    unsigned tmp;
    asm volatile("atom.release.gpu.global.exch.b32 %0, [%1], %2;"
                 : "=r"(tmp) : "l"(p), "r"(v) : "memory");
}

// ---------------- mma.sync helper ----------------
__device__ __forceinline__ void hmma16816(float& c0, float& c1, float& c2, float& c3,
                                          uint32_t a0, uint32_t a1, uint32_t a2, uint32_t a3,
                                          uint32_t b0, uint32_t b1) {
    asm("mma.sync.aligned.m16n8k16.row.col.f32.bf16.bf16.f32 "
        "{%0,%1,%2,%3}, {%4,%5,%6,%7}, {%8,%9}, {%0,%1,%2,%3};"
        : "+f"(c0), "+f"(c1), "+f"(c2), "+f"(c3)
        : "r"(a0), "r"(a1), "r"(a2), "r"(a3), "r"(b0), "r"(b1));
}

// ---------------------------------------------------------------------------
// bf16 split kernels (one-time)
// ---------------------------------------------------------------------------
__global__ __launch_bounds__(256)
void split_x_kernel(const float* __restrict__ X)
{
    size_t i4 = (size_t)blockIdx.x * 256 + threadIdx.x;    // float4 index
    const float4 v = ((const float4*)X)[i4];
    float f[4] = {v.x, v.y, v.z, v.w};
    unsigned short h[4], l[4];
    #pragma unroll
    for (int q = 0; q < 4; q++) {
        __nv_bfloat16 hb = __float2bfloat16(f[q]);
        float lo = f[q] - __bfloat162float(hb);
        __nv_bfloat16 lb = __float2bfloat16(lo);
        h[q] = *(unsigned short*)&hb;
        l[q] = *(unsigned short*)&lb;
    }
    ((uint2*)g_Xh)[i4] = make_uint2((unsigned)h[0] | ((unsigned)h[1] << 16),
                                    (unsigned)h[2] | ((unsigned)h[3] << 16));
    ((uint2*)g_Xl)[i4] = make_uint2((unsigned)l[0] | ((unsigned)l[1] << 16),
                                    (unsigned)l[2] | ((unsigned)l[3] << 16));
}

__global__ __launch_bounds__(256)
void split_wfT_kernel(const float* __restrict__ Wf)
{
    int idx = blockIdx.x * 256 + threadIdx.x;   // 1048576 total
    int k = idx >> 11;            // 0..511
    int n = idx & 2047;           // 0..2047  (coalesced read)
    float v = Wf[(size_t)k * G4_SZ + n];
    __nv_bfloat16 hb = __float2bfloat16(v);
    float lo = v - __bfloat162float(hb);
    g_Bh[(size_t)n * NI_SZ + k] = hb;
    g_Bl[(size_t)n * NI_SZ + k] = __float2bfloat16(lo);
}

// ---------------------------------------------------------------------------
// h0 transpose: g_hT[0][k*128+b] = h0[b*512+k]
// ---------------------------------------------------------------------------
__global__ __launch_bounds__(256)
void h0_transpose_kernel(const float* __restrict__ h0)
{
    int idx = blockIdx.x * 256 + threadIdx.x;   // 65536 total
    int k = idx >> 7, b = idx & 127;
    g_hT[0][idx] = h0[b * D_SZ + k];
}

// ---------------------------------------------------------------------------
// Phase 1: intern = X@Wf + bf via mma.sync bf16 split GEMM.
// Effective K' = 1536 (3 segments: AhBh, AhBl, AlBh), planes indexed per seg.
// CTA 128x128, 256 thr = 8 warps (2m x 4n), warp tile 64x32 (16 frags).
// 24 k-chunks of 64, register-prefetch single-buffer staging.
// ---------------------------------------------------------------------------
#define APAD 72    // bf16 per row (64 + 8 pad): frag LDS conflict-free

__global__ __launch_bounds__(256)
void gemm_mma_kernel(const float* __restrict__ bf)
{
    __shared__ __align__(16) unsigned short A_s[128 * APAD];
    __shared__ __align__(16) unsigned short B_s[128 * APAD];

    const int t = threadIdx.x;
    const int wid = t >> 5, lane = t & 31;
    const int g  = lane >> 2;        // group 0..7
    const int tig = lane & 3;        // thread-in-group
    const int n0 = blockIdx.x * 128;
    const int m0 = blockIdx.y * 128;
    const int wm = wid & 1;          // m-half (64 rows)
    const int wn = wid >> 1;         // n-quarter (32 cols)

    // staging map: 4 uint4 per thread per tile per chunk
    const int s_row = t >> 1;                 // shared by u via +? (idx = u*256+t)
    // we recompute per-u below to keep it simple

    float c[4][4][4];
    #pragma unroll
    for (int fm = 0; fm < 4; fm++)
        #pragma unroll
        for (int fn = 0; fn < 4; fn++)
            #pragma unroll
            for (int q = 0; q < 4; q++) c[fm][fn][q] = 0.f;

    // preload chunk 0
    uint4 av[4], bv[4];
    {
        const __nv_bfloat16* Ap = g_Xh;   // seg 0
        const __nv_bfloat16* Bp = g_Bh;
        #pragma unroll
        for (int u = 0; u < 4; u++) {
            int idx = u * 256 + t;
            int row = idx >> 3, kq = (idx & 7) * 8;
            av[u] = *(const uint4*)(Ap + (size_t)(m0 + row) * NI_SZ + kq);
            bv[u] = *(const uint4*)(Bp + (size_t)(n0 + row) * NI_SZ + kq);
        }
    }

    for (int ci = 0; ci < 24; ci++) {
        __syncthreads();
        #pragma unroll
        for (int u = 0; u < 4; u++) {
            int idx = u * 256 + t;
            int row = idx >> 3, kq = (idx & 7) * 8;
            *(uint4*)&A_s[row * APAD + kq] = av[u];
            *(uint4*)&B_s[row * APAD + kq] = bv[u];
        }
        __syncthreads();

        // prefetch next chunk
        if (ci < 23) {
            int cn = ci + 1;
            int seg = cn >> 3;
            int k_in = (cn & 7) * 64;
            const __nv_bfloat16* Ap = (seg < 2) ? g_Xh : g_Xl;
            const __nv_bfloat16* Bp = (seg == 1) ? g_Bl : g_Bh;
            #pragma unroll
            for (int u = 0; u < 4; u++) {
                int idx = u * 256 + t;
                int row = idx >> 3, kq = (idx & 7) * 8;
                av[u] = *(const uint4*)(Ap + (size_t)(m0 + row) * NI_SZ + k_in + kq);
                bv[u] = *(const uint4*)(Bp + (size_t)(n0 + row) * NI_SZ + k_in + kq);
            }
        }

        // compute: 4 k16 steps
        #pragma unroll
        for (int ks = 0; ks < 4; ks++) {
            const int kb = ks * 16 + tig * 2;
            uint32_t afr[4][4], bfr[4][2];
            #pragma unroll
            for (int fm = 0; fm < 4; fm++) {
                int r0 = wm * 64 + fm * 16 + g;
                afr[fm][0] = *(const uint32_t*)&A_s[r0 * APAD + kb];
                afr[fm][1] = *(const uint32_t*)&A_s[(r0 + 8) * APAD + kb];
                afr[fm][2] = *(const uint32_t*)&A_s[r0 * APAD + kb + 8];
                afr[fm][3] = *(const uint32_t*)&A_s[(r0 + 8) * APAD + kb + 8];
            }
            #pragma unroll
            for (int fn = 0; fn < 4; fn++) {
                int nr = wn * 32 + fn * 8 + g;
                bfr[fn][0] = *(const uint32_t*)&B_s[nr * APAD + kb];
                bfr[fn][1] = *(const uint32_t*)&B_s[nr * APAD + kb + 8];
            }
            #pragma unroll
            for (int fm = 0; fm < 4; fm++)
                #pragma unroll
                for (int fn = 0; fn < 4; fn++)
                    hmma16816(c[fm][fn][0], c[fm][fn][1], c[fm][fn][2], c[fm][fn][3],
                              afr[fm][0], afr[fm][1], afr[fm][2], afr[fm][3],
                              bfr[fn][0], bfr[fn][1]);
        }
    }

    // ---- epilogue: bias + store
    #pragma unroll
    for (int fn = 0; fn < 4; fn++) {
        int col = n0 + wn * 32 + fn * 8 + tig * 2;
        float2 bb = *(const float2*)(bf + col);
        #pragma unroll
        for (int fm = 0; fm < 4; fm++) {
            int r0 = m0 + wm * 64 + fm * 16 + g;
            float2 v0 = make_float2(c[fm][fn][0] + bb.x, c[fm][fn][1] + bb.y);
            float2 v1 = make_float2(c[fm][fn][2] + bb.x, c[fm][fn][3] + bb.y);
            *(float2*)(g_intern + (size_t)r0 * G4_SZ + col)       = v0;
            *(float2*)(g_intern + (size_t)(r0 + 8) * G4_SZ + col) = v1;
        }
    }
}

// ---------------------------------------------------------------------------
// Phase 2: persistent LSTM (R8 structure — best measured variant).
// 128 CTAs (1/SM), 512 threads = 16 warps = 16 k-splits, flag-based sync.
// ---------------------------------------------------------------------------
#define THREADS 512
#define WROW 68
#define HROW 36
#define WR_F (512 * WROW)
#define H_F  (512 * HROW)
#define SMEM_F (WR_F + H_F)

__global__ __launch_bounds__(THREADS, 1)
void lstm_persistent_kernel(const float* __restrict__ hT0,
                            const float* __restrict__ c0,
                            const float* __restrict__ iv,
                            const float* __restrict__ Wr,
                            float* __restrict__ Y,
                            float* __restrict__ C,
                            float* __restrict__ d_fin)
{
    extern __shared__ __align__(16) float smem[];
    float* Ws  = smem;
    float* Hs  = smem + WR_F;
    float* red = Hs;

    const int t    = threadIdx.x;
    const int bid  = blockIdx.x;
    const int j0   = (bid & 31) * 16;
    const int bm0  = (bid >> 5) * 32;
    const int grp  = bid >> 5;

    const int ks   = t >> 5;
    const int lane = t & 31;
    const int jq   = lane >> 3;
    const int gh   = (lane >> 2) & 1;
    const int bg   = lane & 3;
    const int jp0  = jq * 2;
    const int wboff = jp0 * 8 + (jp0 >> 2) * 4 + gh * 4;
    const int hboff = bg * 8;

    const int b_l = t >> 4, jl = t & 15;
    const int b_g = bm0 + b_l, j_g = j0 + jl;
    const int laneA = (jl >> 2) * 8 + (b_l >> 3);
    const int eoff4 = laneA * 68 + (b_l & 7) * 8 + ((jl >> 1) & 1) * 4;
    const int p_odd = jl & 1;
    float c_reg = __ldcg(c0 + (size_t)b_g * D_SZ + j_g);

    const unsigned fbase = g_flag[bid * 32];
    const unsigned* fp0 = &g_flag[(grp * 32 + 2 * ks) * 32];
    const unsigned* fp1 = &g_flag[(grp * 32 + 2 * ks + 1) * 32];

    #pragma unroll
    for (int u = 0; u < 16; u++) {
        int idx = u * THREADS + t;
        int kk2 = idx >> 4;
        int rem = idx & 15;
        int g = rem >> 2, jqs = rem & 3;
        float4 v = __ldcg((const float4*)(Wr + (size_t)kk2 * G4_SZ + g * D_SZ + j0 + jqs * 4));
        int jpA = jqs * 2, jpB = jqs * 2 + 1;
        float* dA = Ws + kk2 * WROW + jpA * 8 + (jpA >> 2) * 4 + g * 2;
        float* dB = Ws + kk2 * WROW + jpB * 8 + (jpB >> 2) * 4 + g * 2;
        dA[0] = v.x; dA[1] = v.y;
        dB[0] = v.z; dB[1] = v.w;
    }
    __syncthreads();

    const int s_r0 = ks * 32 + (lane >> 3);
    const int s_bq = (lane & 7) * 4;

    const float* itp = g_intern + (size_t)b_g * G4_SZ + j_g;
    float in0 = __ldcg(itp), in1 = __ldcg(itp + 512);
    float in2 = __ldcg(itp + 1024), in3 = __ldcg(itp + 1536);
    float mval = __ldcg(iv + b_g);

    for (int step = 0; step < T_STEPS; step++) {
        const float* hT_in  = g_hT[step & 1];
        float*       hT_out = g_hT[(step + 1) & 1];

        if (step > 0) {
            unsigned need = fbase + (unsigned)step;
            if ((int)(ld_acq(fp0) - need) < 0)
                do { __nanosleep(20); } while ((int)(ld_acq(fp0) - need) < 0);
            if ((int)(ld_acq(fp1) - need) < 0)
                do { __nanosleep(20); } while ((int)(ld_acq(fp1) - need) < 0);
        }

        {
            float4 hv[8];
            #pragma unroll
            for (int u = 0; u < 8; u++)
                hv[u] = __ldcg((const float4*)(hT_in +
                          (size_t)(s_r0 + u * 4) * B_SZ + bm0 + s_bq));
            #pragma unroll
            for (int u = 0; u < 8; u++)
                *(float4*)(Hs + (s_r0 + u * 4) * HROW + s_bq) = hv[u];
        }
        __syncwarp();

        u64 acc[8][4];
        #pragma unroll
        for (int i = 0; i < 8; i++)
            #pragma unroll
            for (int j = 0; j < 4; j++) acc[i][j] = 0ull;

        const float* hrow = Hs + (ks * 32) * HROW + hboff;
        const float* wrow = Ws + (ks * 32) * WROW + wboff;
        #pragma unroll 8
        for (int m = 0; m < 32; m++) {
            float4 h0v = *(const float4*)(hrow);
            float4 h1v = *(const float4*)(hrow + 4);
            ulonglong2 w0 = *(const ulonglong2*)(wrow);
            ulonglong2 w1 = *(const ulonglong2*)(wrow + 8);
            hrow += HROW; wrow += WROW;
            u64 wd[4] = {w0.x, w0.y, w1.x, w1.y};
            u64 hd[8] = {dup2(h0v.x), dup2(h0v.y), dup2(h0v.z), dup2(h0v.w),
                         dup2(h1v.x), dup2(h1v.y), dup2(h1v.z), dup2(h1v.w)};
            #pragma unroll
            for (int i = 0; i < 8; i++)
                #pragma unroll
                for (int j = 0; j < 4; j++)
                    ffma2(acc[i][j], hd[i], wd[j]);
        }

        __syncthreads();
        if (ks >= 8) {
            float* p = red + (ks - 8) * 2176 + lane * 68;
            #pragma unroll
            for (int i = 0; i < 8; i++) {
                *(ulonglong2*)(p + i * 8)     = make_ulonglong2(acc[i][0], acc[i][1]);
                *(ulonglong2*)(p + i * 8 + 4) = make_ulonglong2(acc[i][2], acc[i][3]);
            }
        }
        __syncthreads();
        if (ks < 8) {
            float* p = red + ks * 2176 + lane * 68;
            #pragma unroll
            for (int i = 0; i < 8; i++) {
                ulonglong2 v0 = *(ulonglong2*)(p + i * 8);
                ulonglong2 v1 = *(ulonglong2*)(p + i * 8 + 4);
                v0.x = add2(v0.x, acc[i][0]);
                v0.y = add2(v0.y, acc[i][1]);
                v1.x = add2(v1.x, acc[i][2]);
                v1.y = add2(v1.y, acc[i][3]);
                *(ulonglong2*)(p + i * 8)     = v0;
                *(ulonglong2*)(p + i * 8 + 4) = v1;
            }
        }
        __syncthreads();

        float y_out;
        {
            u64 sA0 = 0ull, sA1 = 0ull, sB0 = 0ull, sB1 = 0ull;
            #pragma unroll
            for (int wi = 0; wi < 8; wi++) {
                const float* p = red + wi * 2176;
                ulonglong2 vA = *(const ulonglong2*)(p + eoff4);
                ulonglong2 vB = *(const ulonglong2*)(p + eoff4 + 272);
                sA0 = add2(sA0, vA.x);
                sA1 = add2(sA1, vA.y);
                sB0 = add2(sB0, vB.x);
                sB1 = add2(sB1, vB.y);
            }
            float2 a0 = unpack2(sA0), a1 = unpack2(sA1);
            float2 b0 = unpack2(sB0), b1 = unpack2(sB1);
            float z0 = p_odd ? a0.y : a0.x;
            float z1 = p_odd ? a1.y : a1.x;
            float z2 = p_odd ? b0.y : b0.x;
            float z3 = p_odd ? b1.y : b1.x;

            float zc = z0 + in0;
            float zi = z1 + in1;
            float zf = z2 + in2;
            float zo = z3 + in3;

            zc = fminf(fmaxf(zc, -30.f), 30.f);
            float ec  = __expf(-2.f * zc);
            float cin = (1.f - ec) / (1.f + ec);
            float ig  = 1.f / (1.f + __expf(-zi));
            float fg  = 1.f / (1.f + __expf(-zf));
            float og  = 1.f / (1.f + __expf(-zo));

            float m    = mval;
            float cnew = m * (c_reg * fg + cin * ig) + (1.f - m) * c_reg;
            c_reg = cnew;
            float ct = fminf(fmaxf(cnew, -30.f), 30.f);
            float e2 = __expf(-2.f * ct);
            y_out = m * (og * (1.f - e2) / (1.f + e2));
        }

        if (step + 1 < T_STEPS)
            hT_out[(size_t)j_g * B_SZ + b_g] = y_out;
        __syncthreads();
        if (step + 1 < T_STEPS && t == 0)
            st_release_exch(&g_flag[bid * 32], fbase + (unsigned)step + 1);

        {
            size_t o = (size_t)step * (B_SZ * D_SZ) + (size_t)b_g * D_SZ + j_g;
            Y[o] = y_out;
            C[o] = c_reg;
            if (step == T_STEPS - 1) d_fin[(size_t)b_g * D_SZ + j_g] = c_reg;
        }

        if (step + 1 < T_STEPS) {
            const float* itn = g_intern + (size_t)(step + 1) * (B_SZ * G4_SZ)
                             + (size_t)b_g * G4_SZ + j_g;
            in0 = __ldcg(itn);
            in1 = __ldcg(itn + 512);
            in2 = __ldcg(itn + 1024);
            in3 = __ldcg(itn + 1536);
            mval = __ldcg(iv + (size_t)(step + 1) * B_SZ + b_g);
        }
    }
}

// ---------------------------------------------------------------------------
// Launch. Inputs: X, Wf, Wr, bf, i, h0, c0. Output: Y[T,B,D]|C[T,B,D]|d[B,D]
// ---------------------------------------------------------------------------
extern "C" void kernel_launch(void* const* d_in, const int* in_sizes, int n_in,
                              void* d_out, int out_size)
{
    (void)in_sizes; (void)n_in; (void)out_size;
    const float* X  = (const float*)d_in[0];
    const float* Wf = (const float*)d_in[1];
    const float* Wr = (const float*)d_in[2];
    const float* bf = (const float*)d_in[3];
    const float* iv = (const float*)d_in[4];
    const float* h0 = (const float*)d_in[5];
    const float* c0 = (const float*)d_in[6];

    float* out  = (float*)d_out;
    float* Y    = out;
    float* C    = out + (size_t)T_STEPS * B_SZ * D_SZ;
    float* dfin = C   + (size_t)T_STEPS * B_SZ * D_SZ;

    float* hT0; cudaGetSymbolAddress((void**)&hT0, g_hT);

    // one-time bf16 splits + h0 transpose
    split_x_kernel<<<(T_STEPS * B_SZ * NI_SZ) / (4 * 256), 256>>>(X);
    split_wfT_kernel<<<(NI_SZ * G4_SZ) / 256, 256>>>(Wf);
    h0_transpose_kernel<<<256, 256>>>(h0);

    // tensor-core (mma.sync) GEMM: intern = X@Wf + bf
    dim3 gg(G4_SZ / 128, (T_STEPS * B_SZ) / 128);   // (16, 512)
    gemm_mma_kernel<<<gg, 256>>>(bf);

    // persistent recurrence
    cudaFuncSetAttribute(lstm_persistent_kernel,
                         cudaFuncAttributeMaxDynamicSharedMemorySize,
                         SMEM_F * (int)sizeof(float));
    lstm_persistent_kernel<<<128, THREADS, SMEM_F * sizeof(float)>>>(
        hT0, c0, iv, Wr, Y, C, dfin);
}

// round 13
// speedup vs baseline: 1.5372x; 1.3001x over previous
#include <cuda_runtime.h>
#include <cuda_bf16.h>
#include <cstdint>
#include <math.h>

#define T_STEPS 512
#define B_SZ    128
#define NI_SZ   512
#define D_SZ    512
#define G4_SZ   2048   // 4*D

typedef unsigned long long u64;

// Scratch (device globals: allocation-free rule workaround)
__device__ float g_intern[(size_t)T_STEPS * B_SZ * G4_SZ];
__device__ uint32_t g_hpk[2][(size_t)B_SZ * D_SZ];   // packed bf16 hi|lo h, [b][k], ping-pong
__device__ unsigned g_flag[128 * 32];                // per-CTA produce flag (128B padded)
// bf16 split planes for the phase-1 GEMM
__device__ __nv_bfloat16 g_Xh[(size_t)T_STEPS * B_SZ * NI_SZ];
__device__ __nv_bfloat16 g_Xl[(size_t)T_STEPS * B_SZ * NI_SZ];
__device__ __nv_bfloat16 g_Bh[(size_t)G4_SZ * NI_SZ];   // Wf^T hi  [n][k]
__device__ __nv_bfloat16 g_Bl[(size_t)G4_SZ * NI_SZ];   // Wf^T lo

// ---------------- helpers ----------------
__device__ __forceinline__ unsigned ld_acq(const unsigned* p) {
    unsigned v;
    asm volatile("ld.acquire.gpu.global.u32 %0, [%1];" : "=r"(v) : "l"(p) : "memory");
    return v;
}
__device__ __forceinline__ void st_release_exch(unsigned* p, unsigned v) {
    unsigned tmp;
    asm volatile("atom.release.gpu.global.exch.b32 %0, [%1], %2;"
                 : "=r"(tmp) : "l"(p), "r"(v) : "memory");
}
__device__ __forceinline__ void hmma16816(float& c0, float& c1, float& c2, float& c3,
                                          uint32_t a0, uint32_t a1, uint32_t a2, uint32_t a3,
                                          uint32_t b0, uint32_t b1) {
    asm("mma.sync.aligned.m16n8k16.row.col.f32.bf16.bf16.f32 "
        "{%0,%1,%2,%3}, {%4,%5,%6,%7}, {%8,%9}, {%0,%1,%2,%3};"
        : "+f"(c0), "+f"(c1), "+f"(c2), "+f"(c3)
        : "r"(a0), "r"(a1), "r"(a2), "r"(a3), "r"(b0), "r"(b1));
}
__device__ __forceinline__ uint32_t pack_split(float f) {
    __nv_bfloat16 hb = __float2bfloat16(f);
    float rem = f - __bfloat162float(hb);
    __nv_bfloat16 lb = __float2bfloat16(rem);
    return (uint32_t)*(unsigned short*)&hb | ((uint32_t)*(unsigned short*)&lb << 16);
}

// ---------------------------------------------------------------------------
// One-time prep kernels
// ---------------------------------------------------------------------------
__global__ __launch_bounds__(256)
void split_x_kernel(const float* __restrict__ X)
{
    size_t i4 = (size_t)blockIdx.x * 256 + threadIdx.x;
    const float4 v = ((const float4*)X)[i4];
    float f[4] = {v.x, v.y, v.z, v.w};
    unsigned short h[4], l[4];
    #pragma unroll
    for (int q = 0; q < 4; q++) {
        __nv_bfloat16 hb = __float2bfloat16(f[q]);
        float lo = f[q] - __bfloat162float(hb);
        __nv_bfloat16 lb = __float2bfloat16(lo);
        h[q] = *(unsigned short*)&hb;
        l[q] = *(unsigned short*)&lb;
    }
    ((uint2*)g_Xh)[i4] = make_uint2((unsigned)h[0] | ((unsigned)h[1] << 16),
                                    (unsigned)h[2] | ((unsigned)h[3] << 16));
    ((uint2*)g_Xl)[i4] = make_uint2((unsigned)l[0] | ((unsigned)l[1] << 16),
                                    (unsigned)l[2] | ((unsigned)l[3] << 16));
}

__global__ __launch_bounds__(256)
void split_wfT_kernel(const float* __restrict__ Wf)
{
    int idx = blockIdx.x * 256 + threadIdx.x;
    int k = idx >> 11;
    int n = idx & 2047;
    float v = Wf[(size_t)k * G4_SZ + n];
    __nv_bfloat16 hb = __float2bfloat16(v);
    float lo = v - __bfloat162float(hb);
    g_Bh[(size_t)n * NI_SZ + k] = hb;
    g_Bl[(size_t)n * NI_SZ + k] = __float2bfloat16(lo);
}

__global__ __launch_bounds__(256)
void h0_pack_kernel(const float* __restrict__ h0)
{
    int idx = blockIdx.x * 256 + threadIdx.x;   // 65536
    g_hpk[0][idx] = pack_split(h0[idx]);        // [b][k] natural layout
}

// ---------------------------------------------------------------------------
// Phase 1: intern = X@Wf + bf via mma.sync bf16 split GEMM (R12, proven)
// ---------------------------------------------------------------------------
#define APAD 72

__global__ __launch_bounds__(256)
void gemm_mma_kernel(const float* __restrict__ bf)
{
    __shared__ __align__(16) unsigned short A_s[128 * APAD];
    __shared__ __align__(16) unsigned short B_s[128 * APAD];

    const int t = threadIdx.x;
    const int wid = t >> 5, lane = t & 31;
    const int g  = lane >> 2;
    const int tig = lane & 3;
    const int n0 = blockIdx.x * 128;
    const int m0 = blockIdx.y * 128;
    const int wm = wid & 1;
    const int wn = wid >> 1;

    float c[4][4][4];
    #pragma unroll
    for (int fm = 0; fm < 4; fm++)
        #pragma unroll
        for (int fn = 0; fn < 4; fn++)
            #pragma unroll
            for (int q = 0; q < 4; q++) c[fm][fn][q] = 0.f;

    uint4 av[4], bv[4];
    {
        #pragma unroll
        for (int u = 0; u < 4; u++) {
            int idx = u * 256 + t;
            int row = idx >> 3, kq = (idx & 7) * 8;
            av[u] = *(const uint4*)(g_Xh + (size_t)(m0 + row) * NI_SZ + kq);
            bv[u] = *(const uint4*)(g_Bh + (size_t)(n0 + row) * NI_SZ + kq);
        }
    }

    for (int ci = 0; ci < 24; ci++) {
        __syncthreads();
        #pragma unroll
        for (int u = 0; u < 4; u++) {
            int idx = u * 256 + t;
            int row = idx >> 3, kq = (idx & 7) * 8;
            *(uint4*)&A_s[row * APAD + kq] = av[u];
            *(uint4*)&B_s[row * APAD + kq] = bv[u];
        }
        __syncthreads();

        if (ci < 23) {
            int cn = ci + 1;
            int seg = cn >> 3;
            int k_in = (cn & 7) * 64;
            const __nv_bfloat16* Ap = (seg < 2) ? g_Xh : g_Xl;
            const __nv_bfloat16* Bp = (seg == 1) ? g_Bl : g_Bh;
            #pragma unroll
            for (int u = 0; u < 4; u++) {
                int idx = u * 256 + t;
                int row = idx >> 3, kq = (idx & 7) * 8;
                av[u] = *(const uint4*)(Ap + (size_t)(m0 + row) * NI_SZ + k_in + kq);
                bv[u] = *(const uint4*)(Bp + (size_t)(n0 + row) * NI_SZ + k_in + kq);
            }
        }

        #pragma unroll
        for (int ks = 0; ks < 4; ks++) {
            const int kb = ks * 16 + tig * 2;
            uint32_t afr[4][4], bfr[4][2];
            #pragma unroll
            for (int fm = 0; fm < 4; fm++) {
                int r0 = wm * 64 + fm * 16 + g;
                afr[fm][0] = *(const uint32_t*)&A_s[r0 * APAD + kb];
                afr[fm][1] = *(const uint32_t*)&A_s[(r0 + 8) * APAD + kb];
                afr[fm][2] = *(const uint32_t*)&A_s[r0 * APAD + kb + 8];
                afr[fm][3] = *(const uint32_t*)&A_s[(r0 + 8) * APAD + kb + 8];
            }
            #pragma unroll
            for (int fn = 0; fn < 4; fn++) {
                int nr = wn * 32 + fn * 8 + g;
                bfr[fn][0] = *(const uint32_t*)&B_s[nr * APAD + kb];
                bfr[fn][1] = *(const uint32_t*)&B_s[nr * APAD + kb + 8];
            }
            #pragma unroll
            for (int fm = 0; fm < 4; fm++)
                #pragma unroll
                for (int fn = 0; fn < 4; fn++)
                    hmma16816(c[fm][fn][0], c[fm][fn][1], c[fm][fn][2], c[fm][fn][3],
                              afr[fm][0], afr[fm][1], afr[fm][2], afr[fm][3],
                              bfr[fn][0], bfr[fn][1]);
        }
    }

    #pragma unroll
    for (int fn = 0; fn < 4; fn++) {
        int col = n0 + wn * 32 + fn * 8 + tig * 2;
        float2 bb = *(const float2*)(bf + col);
        #pragma unroll
        for (int fm = 0; fm < 4; fm++) {
            int r0 = m0 + wm * 64 + fm * 16 + g;
            float2 v0 = make_float2(c[fm][fn][0] + bb.x, c[fm][fn][1] + bb.y);
            float2 v1 = make_float2(c[fm][fn][2] + bb.x, c[fm][fn][3] + bb.y);
            *(float2*)(g_intern + (size_t)r0 * G4_SZ + col)       = v0;
            *(float2*)(g_intern + (size_t)(r0 + 8) * G4_SZ + col) = v1;
        }
    }
}

// ---------------------------------------------------------------------------
// Phase 2: persistent LSTM with HMMA recurrence.
// 128 CTAs (1/SM), 512 threads = 16 warps = 4 n-groups x 4 k-quarters.
// Per CTA: M=32 b, N=64 cols (16 j x 4 gates, col = jl*4+g), K=512 x 3 passes.
// Wr bf16 hi/lo in smem (persistent); h arrives packed bf16 hi|lo in gmem,
// unpacked during staging. Fold: 2 fp32 z-regions organized by cell.
// ---------------------------------------------------------------------------
#define THREADS 512
#define KPAD 520                      // bf16 per smem row (512 + 8)
#define SB_HI 0                       // B_hi: 64*520*2 = 66560 B
#define SB_LO 66560
#define SA_HI 133120                  // A_hi: 32*520*2 = 33280 B (fold aliases)
#define SA_LO 166400
#define SMEM_BYTES 199680
#define ZROW 68                       // fold row stride (floats)
#define ZREG 2176                     // 32*68 floats per region

__global__ __launch_bounds__(THREADS, 1)
void lstm_persistent_kernel(const float* __restrict__ c0,
                            const float* __restrict__ iv,
                            const float* __restrict__ Wr,
                            float* __restrict__ Y,
                            float* __restrict__ C,
                            float* __restrict__ d_fin)
{
    extern __shared__ char sm[];
    unsigned short* Bh_s = (unsigned short*)(sm + SB_HI);
    unsigned short* Bl_s = (unsigned short*)(sm + SB_LO);
    unsigned short* Ah_s = (unsigned short*)(sm + SA_HI);
    unsigned short* Al_s = (unsigned short*)(sm + SA_LO);
    float* zbuf = (float*)(sm + SA_HI);   // fold regions alias A_hi

    const int t    = threadIdx.x;
    const int bid  = blockIdx.x;
    const int j0   = (bid & 31) * 16;
    const int bm0  = (bid >> 5) * 32;
    const int grp  = bid >> 5;

    const int w    = t >> 5;
    const int lane = t & 31;
    const int ngrp = w & 3;            // n-group: cols [ngrp*16, +16)
    const int kq   = w >> 2;           // k-quarter: k [kq*128, +128)
    const int g8   = lane >> 2;
    const int tig  = lane & 3;

    // epilogue cell (one per thread)
    const int b_l = t >> 4, jl = t & 15;
    const int b_g = bm0 + b_l, j_g = j0 + jl;
    float c_reg = __ldcg(c0 + (size_t)b_g * D_SZ + j_g);

    // flags: warp w consumes j-blocks {2w, 2w+1} of this b-group
    const unsigned fbase = g_flag[bid * 32];
    const unsigned* fp0 = &g_flag[(grp * 32 + 2 * w) * 32];
    const unsigned* fp1 = &g_flag[(grp * 32 + 2 * w + 1) * 32];

    // ---- one-time: stage Wr slice as bf16 hi/lo planes
    #pragma unroll
    for (int u = 0; u < 16; u++) {
        int idx = u * THREADS + t;       // 8192 float4 slots
        int k  = idx >> 4;
        int g  = (idx >> 2) & 3;
        int jq = idx & 3;
        float4 v = __ldcg((const float4*)(Wr + (size_t)k * G4_SZ + g * D_SZ + j0 + jq * 4));
        const float* fv = &v.x;
        #pragma unroll
        for (int jj = 0; jj < 4; jj++) {
            float f = fv[jj];
            __nv_bfloat16 hb = __float2bfloat16(f);
            float rem = f - __bfloat162float(hb);
            __nv_bfloat16 lb = __float2bfloat16(rem);
            int col = (jq * 4 + jj) * 4 + g;
            Bh_s[col * KPAD + k] = *(unsigned short*)&hb;
            Bl_s[col * KPAD + k] = *(unsigned short*)&lb;
        }
    }
    __syncthreads();

    // h staging map: warp w stages k-slice [32w, +32) of all 32 b
    const int s_bb  = lane & 3;        // b sub-index (row = u*4 + s_bb)
    const int s_kqd = lane >> 2;       // k-quad within slice (0..7)

    // prefetch step 0 epilogue operands
    const float* itp = g_intern + (size_t)b_g * G4_SZ + j_g;
    float in0 = __ldcg(itp), in1 = __ldcg(itp + 512);
    float in2 = __ldcg(itp + 1024), in3 = __ldcg(itp + 1536);
    float mval = __ldcg(iv + b_g);

    for (int step = 0; step < T_STEPS; step++) {
        const uint32_t* hin = g_hpk[step & 1];
        uint32_t*       hot = g_hpk[(step + 1) & 1];

        // ---- wait for my 2 producers
        if (step > 0) {
            unsigned need = fbase + (unsigned)step;
            if ((int)(ld_acq(fp0) - need) < 0)
                do { __nanosleep(20); } while ((int)(ld_acq(fp0) - need) < 0);
            if ((int)(ld_acq(fp1) - need) < 0)
                do { __nanosleep(20); } while ((int)(ld_acq(fp1) - need) < 0);
        }

        // ---- stage h: unpack packed bf16 pairs into hi/lo planes
        {
            const uint32_t* base = hin + (size_t)bm0 * D_SZ + w * 32 + s_kqd * 4;
            #pragma unroll
            for (int u = 0; u < 8; u++) {
                int b = u * 4 + s_bb;
                uint4 v = __ldcg((const uint4*)(base + (size_t)b * D_SZ));
                uint32_t hi01 = __byte_perm(v.x, v.y, 0x5410);
                uint32_t lo01 = __byte_perm(v.x, v.y, 0x7632);
                uint32_t hi23 = __byte_perm(v.z, v.w, 0x5410);
                uint32_t lo23 = __byte_perm(v.z, v.w, 0x7632);
                int off = b * KPAD + w * 32 + s_kqd * 4;
                *(uint2*)&Ah_s[off] = make_uint2(hi01, hi23);
                *(uint2*)&Al_s[off] = make_uint2(lo01, lo23);
            }
        }
        __syncthreads();

        // ---- HMMA mainloop: 3 split passes x 8 k16 steps
        float c[2][2][4];
        #pragma unroll
        for (int mt = 0; mt < 2; mt++)
            #pragma unroll
            for (int nt = 0; nt < 2; nt++)
                #pragma unroll
                for (int q = 0; q < 4; q++) c[mt][nt][q] = 0.f;

        #pragma unroll
        for (int p = 0; p < 3; p++) {
            const unsigned short* As = (p == 2) ? Al_s : Ah_s;
            const unsigned short* Bs = (p == 1) ? Bl_s : Bh_s;
            #pragma unroll
            for (int s = 0; s < 8; s++) {
                const int kb = kq * 128 + s * 16 + tig * 2;
                uint32_t afr[2][4], bfr[2][2];
                #pragma unroll
                for (int mt = 0; mt < 2; mt++) {
                    int r0 = mt * 16 + g8;
                    afr[mt][0] = *(const uint32_t*)&As[r0 * KPAD + kb];
                    afr[mt][1] = *(const uint32_t*)&As[(r0 + 8) * KPAD + kb];
                    afr[mt][2] = *(const uint32_t*)&As[r0 * KPAD + kb + 8];
                    afr[mt][3] = *(const uint32_t*)&As[(r0 + 8) * KPAD + kb + 8];
                }
                #pragma unroll
                for (int nt = 0; nt < 2; nt++) {
                    int nr = ngrp * 16 + nt * 8 + g8;
                    bfr[nt][0] = *(const uint32_t*)&Bs[nr * KPAD + kb];
                    bfr[nt][1] = *(const uint32_t*)&Bs[nr * KPAD + kb + 8];
                }
                #pragma unroll
                for (int mt = 0; mt < 2; mt++)
                    #pragma unroll
                    for (int nt = 0; nt < 2; nt++)
                        hmma16816(c[mt][nt][0], c[mt][nt][1], c[mt][nt][2], c[mt][nt][3],
                                  afr[mt][0], afr[mt][1], afr[mt][2], afr[mt][3],
                                  bfr[nt][0], bfr[nt][1]);
            }
        }

        // ---- fold: kq {2,3} store regions, kq {0,1} add in
        __syncthreads();
        if (kq >= 2) {
            float* z = zbuf + (kq - 2) * ZREG;
            #pragma unroll
            for (int mt = 0; mt < 2; mt++)
                #pragma unroll
                for (int nt = 0; nt < 2; nt++) {
                    int b = mt * 16 + g8;
                    int col = ngrp * 16 + nt * 8 + tig * 2;
                    *(float2*)&z[b * ZROW + col]       = make_float2(c[mt][nt][0], c[mt][nt][1]);
                    *(float2*)&z[(b + 8) * ZROW + col] = make_float2(c[mt][nt][2], c[mt][nt][3]);
                }
        }
        __syncthreads();
        if (kq < 2) {
            float* z = zbuf + kq * ZREG;
            #pragma unroll
            for (int mt = 0; mt < 2; mt++)
                #pragma unroll
                for (int nt = 0; nt < 2; nt++) {
                    int b = mt * 16 + g8;
                    int col = ngrp * 16 + nt * 8 + tig * 2;
                    float2 v0 = *(float2*)&z[b * ZROW + col];
                    float2 v1 = *(float2*)&z[(b + 8) * ZROW + col];
                    v0.x += c[mt][nt][0]; v0.y += c[mt][nt][1];
                    v1.x += c[mt][nt][2]; v1.y += c[mt][nt][3];
                    *(float2*)&z[b * ZROW + col]       = v0;
                    *(float2*)&z[(b + 8) * ZROW + col] = v1;
                }
        }
        __syncthreads();

        // ---- fused epilogue: one cell per thread, gates contiguous
        float y_out;
        {
            float4 z0 = *(const float4*)&zbuf[b_l * ZROW + jl * 4];
            float4 z1 = *(const float4*)&zbuf[ZREG + b_l * ZROW + jl * 4];

            float zc = z0.x + z1.x + in0;
            float zi = z0.y + z1.y + in1;
            float zf = z0.z + z1.z + in2;
            float zo = z0.w + z1.w + in3;

            zc = fminf(fmaxf(zc, -30.f), 30.f);
            float ec  = __expf(-2.f * zc);
            float cin = (1.f - ec) / (1.f + ec);
            float ig  = 1.f / (1.f + __expf(-zi));
            float fg  = 1.f / (1.f + __expf(-zf));
            float og  = 1.f / (1.f + __expf(-zo));

            float m    = mval;
            float cnew = m * (c_reg * fg + cin * ig) + (1.f - m) * c_reg;
            c_reg = cnew;
            float ct = fminf(fmaxf(cnew, -30.f), 30.f);
            float e2 = __expf(-2.f * ct);
            y_out = m * (og * (1.f - e2) / (1.f + e2));
        }

        // ---- publish h(step+1): packed bf16 split, coalesced STG.32
        if (step + 1 < T_STEPS)
            hot[(size_t)b_g * D_SZ + j_g] = pack_split(y_out);
        __syncthreads();   // hT STGs issued + all zbuf reads complete
        if (step + 1 < T_STEPS && t == 0)
            st_release_exch(&g_flag[bid * 32], fbase + (unsigned)step + 1);

        // ---- deferred gmem writes
        {
            size_t o = (size_t)step * (B_SZ * D_SZ) + (size_t)b_g * D_SZ + j_g;
            Y[o] = y_out;
            C[o] = c_reg;
            if (step == T_STEPS - 1) d_fin[(size_t)b_g * D_SZ + j_g] = c_reg;
        }

        // ---- prefetch next step's epilogue operands
        if (step + 1 < T_STEPS) {
            const float* itn = g_intern + (size_t)(step + 1) * (B_SZ * G4_SZ)
                             + (size_t)b_g * G4_SZ + j_g;
            in0 = __ldcg(itn);
            in1 = __ldcg(itn + 512);
            in2 = __ldcg(itn + 1024);
            in3 = __ldcg(itn + 1536);
            mval = __ldcg(iv + (size_t)(step + 1) * B_SZ + b_g);
        }
    }
}

// ---------------------------------------------------------------------------
// Launch. Inputs: X, Wf, Wr, bf, i, h0, c0. Output: Y[T,B,D]|C[T,B,D]|d[B,D]
// ---------------------------------------------------------------------------
extern "C" void kernel_launch(void* const* d_in, const int* in_sizes, int n_in,
                              void* d_out, int out_size)
{
    (void)in_sizes; (void)n_in; (void)out_size;
    const float* X  = (const float*)d_in[0];
    const float* Wf = (const float*)d_in[1];
    const float* Wr = (const float*)d_in[2];
    const float* bf = (const float*)d_in[3];
    const float* iv = (const float*)d_in[4];
    const float* h0 = (const float*)d_in[5];
    const float* c0 = (const float*)d_in[6];

    float* out  = (float*)d_out;
    float* Y    = out;
    float* C    = out + (size_t)T_STEPS * B_SZ * D_SZ;
    float* dfin = C   + (size_t)T_STEPS * B_SZ * D_SZ;

    // one-time prep
    split_x_kernel<<<(T_STEPS * B_SZ * NI_SZ) / (4 * 256), 256>>>(X);
    split_wfT_kernel<<<(NI_SZ * G4_SZ) / 256, 256>>>(Wf);
    h0_pack_kernel<<<256, 256>>>(h0);

    // tensor-core GEMM: intern = X@Wf + bf
    dim3 gg(G4_SZ / 128, (T_STEPS * B_SZ) / 128);   // (16, 512)
    gemm_mma_kernel<<<gg, 256>>>(bf);

    // persistent HMMA recurrence
    cudaFuncSetAttribute(lstm_persistent_kernel,
                         cudaFuncAttributeMaxDynamicSharedMemorySize, SMEM_BYTES);
    lstm_persistent_kernel<<<128, THREADS, SMEM_BYTES>>>(
        c0, iv, Wr, Y, C, dfin);
}